// round 9
// baseline (speedup 1.0000x reference)
#include <cuda_runtime.h>
#include <cuda_bf16.h>

#define EPS 1e-6f
#define ITERS 20

typedef unsigned long long u64;

__device__ __forceinline__ float frcp(float x) {
    float y;
    asm("rcp.approx.ftz.f32 %0, %1;" : "=f"(y) : "f"(x));
    return y;
}
__device__ __forceinline__ u64 pack2(float lo, float hi) {
    u64 r;
    asm("mov.b64 %0, {%1, %2};" : "=l"(r) : "f"(lo), "f"(hi));
    return r;
}
__device__ __forceinline__ void unpack2(u64 v, float& lo, float& hi) {
    asm("mov.b64 {%0, %1}, %2;" : "=f"(lo), "=f"(hi) : "l"(v));
}
__device__ __forceinline__ u64 mul2(u64 a, u64 b) {
    u64 d;
    asm("mul.rn.f32x2 %0, %1, %2;" : "=l"(d) : "l"(a), "l"(b));
    return d;
}
__device__ __forceinline__ u64 add2(u64 a, u64 b) {
    u64 d;
    asm("add.rn.f32x2 %0, %1, %2;" : "=l"(d) : "l"(a), "l"(b));
    return d;
}
__device__ __forceinline__ u64 fma2(u64 a, u64 b, u64 c) {
    u64 d;
    asm("fma.rn.f32x2 %0, %1, %2, %3;" : "=l"(d) : "l"(a), "l"(b), "l"(c));
    return d;
}

// Batched 4-way reciprocal: one MUFU RCP instead of four.
// (R01, R23) = elementwise 1/(T01, T23)
__device__ __forceinline__ void brcp4(u64 T01, u64 T23, u64& R01, u64& R23) {
    float t0, t1, t2, t3;
    unpack2(T01, t0, t1);
    unpack2(T23, t2, t3);
    float u = t0 * t1;
    float v = t2 * t3;
    float q = frcp(u * v);
    float a = q * v;   // 1/(t0*t1)
    float b = q * u;   // 1/(t2*t3)
    R01 = mul2(pack2(a, a), pack2(t1, t0));
    R23 = mul2(pack2(b, b), pack2(t3, t2));
}

__global__ __launch_bounds__(256)
void hc_sinkhorn_kernel(const float* __restrict__ mixes,
                        const float* __restrict__ hc_scale,
                        const float* __restrict__ hc_base,
                        float* __restrict__ out,
                        int n_tok)
{
    __shared__ float sb[24];
    __shared__ float ss[3];
    if (threadIdx.x < 24) sb[threadIdx.x] = hc_base[threadIdx.x];
    if (threadIdx.x < 3)  ss[threadIdx.x] = hc_scale[threadIdx.x];
    __syncthreads();

    const int t = blockIdx.x * blockDim.x + threadIdx.x;
    if (t >= n_tok) return;

    const float4* mp = (const float4*)(mixes + (size_t)t * 24);
    float4 v0 = __ldcs(mp + 0);
    float4 v1 = __ldcs(mp + 1);
    float4 v2 = __ldcs(mp + 2);
    float4 v3 = __ldcs(mp + 3);
    float4 v4 = __ldcs(mp + 4);
    float4 v5 = __ldcs(mp + 5);

    const float s0 = ss[0], s1 = ss[1], s2 = ss[2];

    float4* op = (float4*)out;
    float4* oq = (float4*)(out + (size_t)n_tok * 4);
    float4* oc = (float4*)(out + (size_t)n_tok * 8);

    // ---- pre: sigmoid(x*s0 + b) + EPS — compute and store immediately ----
    {
        float p[4] = {v0.x, v0.y, v0.z, v0.w};
        #pragma unroll
        for (int i = 0; i < 4; i++)
            p[i] = frcp(1.0f + __expf(-fmaf(p[i], s0, sb[i]))) + EPS;
        __stcs(op + t, make_float4(p[0], p[1], p[2], p[3]));
    }

    // ---- post: 2*sigmoid(x*s1 + b) — compute and store immediately ----
    {
        float p[4] = {v1.x, v1.y, v1.z, v1.w};
        #pragma unroll
        for (int i = 0; i < 4; i++)
            p[i] = 2.0f * frcp(1.0f + __expf(-fmaf(p[i], s1, sb[4 + i])));
        __stcs(oq + t, make_float4(p[0], p[1], p[2], p[3]));
    }

    // ---- comb: softmax(rows) + EPS ----
    float m[4][4] = {
        {v2.x, v2.y, v2.z, v2.w},
        {v3.x, v3.y, v3.z, v3.w},
        {v4.x, v4.y, v4.z, v4.w},
        {v5.x, v5.y, v5.z, v5.w},
    };
    #pragma unroll
    for (int i = 0; i < 4; i++) {
        #pragma unroll
        for (int j = 0; j < 4; j++)
            m[i][j] = __expf(fmaf(m[i][j], s2, sb[8 + i * 4 + j]));
        float inv = frcp((m[i][0] + m[i][1]) + (m[i][2] + m[i][3]));
        #pragma unroll
        for (int j = 0; j < 4; j++)
            m[i][j] = fmaf(m[i][j], inv, EPS);  // softmax + EPS
    }

    // ---- Pack m in two layouts (loop-invariant) ----
    // mr[i][h]: row pairs   (m[i][0],m[i][1]) / (m[i][2],m[i][3])
    // mt[j][h]: column pairs (m[0][j],m[1][j]) / (m[2][j],m[3][j])
    u64 mr[4][2], mt[4][2];
    #pragma unroll
    for (int i = 0; i < 4; i++) {
        mr[i][0] = pack2(m[i][0], m[i][1]);
        mr[i][1] = pack2(m[i][2], m[i][3]);
    }
    #pragma unroll
    for (int j = 0; j < 4; j++) {
        mt[j][0] = pack2(m[0][j], m[1][j]);
        mt[j][1] = pack2(m[2][j], m[3][j]);
    }

    // ---- Sinkhorn with diagonal scaling vectors, N_ij = m_ij * r_i * c_j ----
    // Col pass: c_j = 1/(M^T r)_j ; Row pass: r_i = 1/(M c)_i.
    // (EPS in denominators dropped: <=1e-6 relative per pass, well under tolerance.)
    u64 r01, r23, c01, c23;

    // First col-normalize with r = 1: S_j = sum_i m_ij — col sums are sums of row-pairs.
    {
        u64 S01 = add2(add2(mr[0][0], mr[1][0]), add2(mr[2][0], mr[3][0]));
        u64 S23 = add2(add2(mr[0][1], mr[1][1]), add2(mr[2][1], mr[3][1]));
        brcp4(S01, S23, c01, c23);
    }
    r01 = pack2(1.0f, 1.0f);
    r23 = r01;

    #pragma unroll 1
    for (int it = 0; it < ITERS - 1; it++) {
        // Row pass: (T0,T1) = sum_j mt[j][0]*c_j ; (T2,T3) = sum_j mt[j][1]*c_j
        float c0, c1, c2, c3;
        unpack2(c01, c0, c1);
        unpack2(c23, c2, c3);
        u64 cb0 = pack2(c0, c0), cb1 = pack2(c1, c1);
        u64 cb2 = pack2(c2, c2), cb3 = pack2(c3, c3);
        u64 T01 = mul2(mt[0][0], cb0);
        u64 T23 = mul2(mt[0][1], cb0);
        T01 = fma2(mt[1][0], cb1, T01);
        T23 = fma2(mt[1][1], cb1, T23);
        T01 = fma2(mt[2][0], cb2, T01);
        T23 = fma2(mt[2][1], cb2, T23);
        T01 = fma2(mt[3][0], cb3, T01);
        T23 = fma2(mt[3][1], cb3, T23);
        brcp4(T01, T23, r01, r23);

        // Col pass: (S0,S1) = sum_i mr[i][0]*r_i ; (S2,S3) = sum_i mr[i][1]*r_i
        float r0, r1, r2, r3;
        unpack2(r01, r0, r1);
        unpack2(r23, r2, r3);
        u64 rb0 = pack2(r0, r0), rb1 = pack2(r1, r1);
        u64 rb2 = pack2(r2, r2), rb3 = pack2(r3, r3);
        u64 S01 = mul2(mr[0][0], rb0);
        u64 S23 = mul2(mr[0][1], rb0);
        S01 = fma2(mr[1][0], rb1, S01);
        S23 = fma2(mr[1][1], rb1, S23);
        S01 = fma2(mr[2][0], rb2, S01);
        S23 = fma2(mr[2][1], rb2, S23);
        S01 = fma2(mr[3][0], rb3, S01);
        S23 = fma2(mr[3][1], rb3, S23);
        brcp4(S01, S23, c01, c23);
    }

    // ---- Epilogue: N_ij = m_ij * r_i * c_j ----
    {
        float r0, r1, r2, r3;
        unpack2(r01, r0, r1);
        unpack2(r23, r2, r3);
        float rr[4] = {r0, r1, r2, r3};
        #pragma unroll
        for (int i = 0; i < 4; i++) {
            u64 rb = pack2(rr[i], rr[i]);
            u64 na = mul2(mul2(mr[i][0], c01), rb);
            u64 nb = mul2(mul2(mr[i][1], c23), rb);
            float n0, n1, n2, n3;
            unpack2(na, n0, n1);
            unpack2(nb, n2, n3);
            __stcs(oc + (size_t)t * 4 + i, make_float4(n0, n1, n2, n3));
        }
    }
}

extern "C" void kernel_launch(void* const* d_in, const int* in_sizes, int n_in,
                              void* d_out, int out_size)
{
    const float* mixes    = (const float*)d_in[0];
    const float* hc_scale = (const float*)d_in[1];
    const float* hc_base  = (const float*)d_in[2];

    const int n_tok = in_sizes[0] / 24;
    const int block = 256;
    const int grid  = (n_tok + block - 1) / block;

    hc_sinkhorn_kernel<<<grid, block>>>(mixes, hc_scale, hc_base, (float*)d_out, n_tok);
}